// round 3
// baseline (speedup 1.0000x reference)
#include <cuda_runtime.h>
#include <cstdint>

#define NB 4
#define NT 2048
#define NC 1024
#define NH 16
#define NHS 64

// ---------------- scratch (static device globals; no runtime alloc) --------
__device__ float g_q[(size_t)NB * NH * NT * NHS];
__device__ float g_k[(size_t)NB * NH * NT * NHS];
__device__ float g_v[(size_t)NB * NH * NT * NHS];
__device__ float g_attn[(size_t)NB * NT * NC];

// ---------------- tf32 helpers ---------------------------------------------
__device__ __forceinline__ uint32_t f2tf(float x) {
    uint32_t r;
    asm("cvt.rna.tf32.f32 %0, %1;" : "=r"(r) : "f"(x));
    return r;
}
__device__ __forceinline__ float tf32r(float x) { return __uint_as_float(f2tf(x)); }

// split x -> tf32 hi + tf32 lo, stored to smem
__device__ __forceinline__ void split_store(float x, float* ph, float* pl) {
    float h = tf32r(x);
    *ph = h;
    *pl = tf32r(x - h);
}
// split in registers (for P which is produced, not loaded)
__device__ __forceinline__ void split2(float x, uint32_t& h, uint32_t& l) {
    h = f2tf(x);
    l = f2tf(x - __uint_as_float(h));
}
__device__ __forceinline__ uint32_t fb(float x) { return __float_as_uint(x); }

__device__ __forceinline__ void mma8(float* d, const uint32_t* a, uint32_t b0, uint32_t b1) {
    asm volatile(
        "mma.sync.aligned.m16n8k8.row.col.f32.tf32.tf32.f32 "
        "{%0,%1,%2,%3}, {%4,%5,%6,%7}, {%8,%9}, {%0,%1,%2,%3};"
        : "+f"(d[0]), "+f"(d[1]), "+f"(d[2]), "+f"(d[3])
        : "r"(a[0]), "r"(a[1]), "r"(a[2]), "r"(a[3]), "r"(b0), "r"(b1));
}

// ---------------- GEMM: C = A(MxK) * B(NxK)^T ------------------------------
// MODE 0 (QKV proj): 3xTF32 (score path, softmax-amplified). Scatter to q/k/v.
// MODE 1 (out proj): 2xTF32 (linear error path). Out = A*Wo^T + bias.
// Pre-split hi/lo smem tiles + register-prefetch double buffering.
template <int MODE>
__global__ void __launch_bounds__(256) gemm_nt_kernel(
    const float* __restrict__ A,
    const float* __restrict__ W0, const float* __restrict__ W1,
    const float* __restrict__ W2,
    const float* __restrict__ bias, float* __restrict__ Out)
{
    extern __shared__ float sm[];
    float (*Ah)[36] = (float(*)[36])(sm);
    float (*Al)[36] = (float(*)[36])(sm + 4608);
    float (*Bh)[36] = (float(*)[36])(sm + 9216);
    float (*Bl)[36] = (float(*)[36])(sm + 13824);

    const int tid  = threadIdx.x;
    const int warp = tid >> 5, lane = tid & 31;
    const int g    = lane >> 2, tg = lane & 3;
    const int wm   = warp >> 2, wn = warp & 3;   // 2 x 4 warps, warp tile 64x32
    const int m0   = blockIdx.y * 128;
    const int nb   = blockIdx.x;

    const float* Ap = (MODE == 0) ? A : (const float*)g_attn;
    const float* Bp;
    int n0, sel = 0;
    if (MODE == 0) {
        sel = nb >> 3;
        Bp  = (sel == 0) ? W0 : (sel == 1) ? W1 : W2;
        n0  = (nb & 7) * 128;
    } else {
        Bp = W0;
        n0 = nb * 128;
    }

    float acc[4][4][4];
#pragma unroll
    for (int a = 0; a < 4; a++)
#pragma unroll
        for (int b = 0; b < 4; b++)
#pragma unroll
            for (int c = 0; c < 4; c++) acc[a][b][c] = 0.f;

    const int lr = tid >> 3;        // 0..31
    const int lc = (tid & 7) << 2;  // 0,4,...,28

    float4 ra[4], rb[4];
#pragma unroll
    for (int i = 0; i < 4; i++) {
        ra[i] = *(const float4*)(Ap + (size_t)(m0 + lr + i * 32) * NC + lc);
        rb[i] = *(const float4*)(Bp + (size_t)(n0 + lr + i * 32) * NC + lc);
    }

    for (int kt = 0; kt < NC; kt += 32) {
        __syncthreads();
        // store prefetched regs -> smem, splitting hi/lo once per element
#pragma unroll
        for (int i = 0; i < 4; i++) {
            int r = lr + i * 32;
            const float* pa = (const float*)&ra[i];
            const float* pb = (const float*)&rb[i];
#pragma unroll
            for (int e = 0; e < 4; e++) {
                split_store(pa[e], &Ah[r][lc + e], &Al[r][lc + e]);
                if (MODE == 0) split_store(pb[e], &Bh[r][lc + e], &Bl[r][lc + e]);
                else           Bh[r][lc + e] = tf32r(pb[e]);
            }
        }
        __syncthreads();
        // prefetch next tile into registers (overlaps with mma below)
        if (kt + 32 < NC) {
#pragma unroll
            for (int i = 0; i < 4; i++) {
                ra[i] = *(const float4*)(Ap + (size_t)(m0 + lr + i * 32) * NC + kt + 32 + lc);
                rb[i] = *(const float4*)(Bp + (size_t)(n0 + lr + i * 32) * NC + kt + 32 + lc);
            }
        }

#pragma unroll
        for (int ks = 0; ks < 4; ks++) {
            const int k0 = ks * 8;
            uint32_t ah[4][4], al[4][4];
#pragma unroll
            for (int mt = 0; mt < 4; mt++) {
                const int r = wm * 64 + mt * 16;
                ah[mt][0] = fb(Ah[r + g][k0 + tg]);         al[mt][0] = fb(Al[r + g][k0 + tg]);
                ah[mt][1] = fb(Ah[r + g + 8][k0 + tg]);     al[mt][1] = fb(Al[r + g + 8][k0 + tg]);
                ah[mt][2] = fb(Ah[r + g][k0 + tg + 4]);     al[mt][2] = fb(Al[r + g][k0 + tg + 4]);
                ah[mt][3] = fb(Ah[r + g + 8][k0 + tg + 4]); al[mt][3] = fb(Al[r + g + 8][k0 + tg + 4]);
            }
#pragma unroll
            for (int nt = 0; nt < 4; nt++) {
                const int cb = wn * 32 + nt * 8;
                uint32_t b0h = fb(Bh[cb + g][k0 + tg]);
                uint32_t b1h = fb(Bh[cb + g][k0 + tg + 4]);
                uint32_t b0l = 0, b1l = 0;
                if (MODE == 0) {
                    b0l = fb(Bl[cb + g][k0 + tg]);
                    b1l = fb(Bl[cb + g][k0 + tg + 4]);
                }
#pragma unroll
                for (int mt = 0; mt < 4; mt++) {
                    mma8(acc[mt][nt], ah[mt], b0h, b1h);
                    mma8(acc[mt][nt], al[mt], b0h, b1h);
                    if (MODE == 0) mma8(acc[mt][nt], ah[mt], b0l, b1l);
                }
            }
        }
    }

    // epilogue
    float* dst = nullptr;
    if (MODE == 0) dst = (sel == 0) ? g_q : (sel == 1) ? g_k : g_v;

#pragma unroll
    for (int mt = 0; mt < 4; mt++) {
        int row = m0 + wm * 64 + mt * 16 + g;
#pragma unroll
        for (int nt = 0; nt < 4; nt++) {
            int col = n0 + wn * 32 + nt * 8 + 2 * tg;
            if (MODE == 0) {
                int bb = row >> 11, t = row & (NT - 1);
                int hh = col >> 6,  d = col & 63;
                float* p = dst + (((size_t)(bb * NH + hh) * NT + t) * NHS) + d;
                *(float2*)p             = make_float2(acc[mt][nt][0], acc[mt][nt][1]);
                *(float2*)(p + 8 * NHS) = make_float2(acc[mt][nt][2], acc[mt][nt][3]);
            } else {
                float2 bv = *(const float2*)(bias + col);
                *(float2*)(Out + (size_t)row * NC + col) =
                    make_float2(acc[mt][nt][0] + bv.x, acc[mt][nt][1] + bv.y);
                *(float2*)(Out + (size_t)(row + 8) * NC + col) =
                    make_float2(acc[mt][nt][2] + bv.x, acc[mt][nt][3] + bv.y);
            }
        }
    }
}

// ---------------- flash attention (causal, scale = +sqrt(HS) = 8) ----------
// Grid: (T/128, B*H). 256 threads = 8 warps; warp w owns rows [16w, 16w+16).
// K/V in 32-key steps, register-prefetched. Q/K pre-split hi/lo in smem
// (3xTF32 scores); V hi-only (2xTF32 PV, linear error path).
__global__ void __launch_bounds__(256) flash_attn_kernel()
{
    extern __shared__ float sm[];
    float (*Qh)[68] = (float(*)[68])(sm);
    float (*Ql)[68] = (float(*)[68])(sm + 8704);
    float (*Kh)[68] = (float(*)[68])(sm + 17408);
    float (*Kl)[68] = (float(*)[68])(sm + 19584);
    float (*Vh)[72] = (float(*)[72])(sm + 21760);
    float (*Ps)[36] = (float(*)[36])(sm + 24064);

    const int tid  = threadIdx.x;
    const int warp = tid >> 5, lane = tid & 31;
    const int g    = lane >> 2, tg = lane & 3;
    const int qi   = blockIdx.x, bh = blockIdx.y;

    const size_t base = (size_t)bh * NT * NHS;
    const float* Qg = g_q + base + (size_t)qi * 128 * NHS;
    const float* Kg = g_k + base;
    const float* Vg = g_v + base;

    // load Q tile once, pre-scaled by sqrt(HS)=8 (exact pow2), pre-split
    for (int i = tid; i < 128 * 16; i += 256) {
        int r = i >> 4, c4 = (i & 15) << 2;
        float4 v = *(const float4*)(Qg + r * 64 + c4);
        split_store(v.x * 8.f, &Qh[r][c4],     &Ql[r][c4]);
        split_store(v.y * 8.f, &Qh[r][c4 + 1], &Ql[r][c4 + 1]);
        split_store(v.z * 8.f, &Qh[r][c4 + 2], &Ql[r][c4 + 2]);
        split_store(v.w * 8.f, &Qh[r][c4 + 3], &Ql[r][c4 + 3]);
    }

    float o[8][4];
#pragma unroll
    for (int i = 0; i < 8; i++)
#pragma unroll
        for (int j = 0; j < 4; j++) o[i][j] = 0.f;
    float mr[2]   = {-1e30f, -1e30f};
    float lsum[2] = {0.f, 0.f};

    const int row0 = qi * 128 + warp * 16 + g;
    const int nkt  = 4 * qi + 4;

    float4 rk[2], rv[2];
#pragma unroll
    for (int j = 0; j < 2; j++) {
        int idx = tid + j * 256;
        int r = idx >> 4, c4 = (idx & 15) << 2;
        rk[j] = *(const float4*)(Kg + (size_t)r * 64 + c4);
        rv[j] = *(const float4*)(Vg + (size_t)r * 64 + c4);
    }

    for (int kt = 0; kt < nkt; kt++) {
        __syncthreads();
        // store prefetched K/V -> smem (split K, round V)
#pragma unroll
        for (int j = 0; j < 2; j++) {
            int idx = tid + j * 256;
            int r = idx >> 4, c4 = (idx & 15) << 2;
            const float* pk = (const float*)&rk[j];
            const float* pv = (const float*)&rv[j];
#pragma unroll
            for (int e = 0; e < 4; e++) {
                split_store(pk[e], &Kh[r][c4 + e], &Kl[r][c4 + e]);
                Vh[r][c4 + e] = tf32r(pv[e]);
            }
        }
        __syncthreads();
        if (kt + 1 < nkt) {
#pragma unroll
            for (int j = 0; j < 2; j++) {
                int idx = tid + j * 256;
                int r = idx >> 4, c4 = (idx & 15) << 2;
                rk[j] = *(const float4*)(Kg + (size_t)((kt + 1) * 32 + r) * 64 + c4);
                rv[j] = *(const float4*)(Vg + (size_t)((kt + 1) * 32 + r) * 64 + c4);
            }
        }

        // warp-level skip of fully-masked key blocks (uniform per warp)
        if (kt * 32 > qi * 128 + warp * 16 + 15) continue;

        // S = Q * K^T  (16x32 per warp), 3xTF32
        float s[4][4];
#pragma unroll
        for (int i = 0; i < 4; i++)
#pragma unroll
            for (int j = 0; j < 4; j++) s[i][j] = 0.f;

#pragma unroll
        for (int ks = 0; ks < 8; ks++) {
            const int k0 = ks * 8, r = warp * 16;
            uint32_t qh_[4], ql_[4];
            qh_[0] = fb(Qh[r + g][k0 + tg]);         ql_[0] = fb(Ql[r + g][k0 + tg]);
            qh_[1] = fb(Qh[r + g + 8][k0 + tg]);     ql_[1] = fb(Ql[r + g + 8][k0 + tg]);
            qh_[2] = fb(Qh[r + g][k0 + tg + 4]);     ql_[2] = fb(Ql[r + g][k0 + tg + 4]);
            qh_[3] = fb(Qh[r + g + 8][k0 + tg + 4]); ql_[3] = fb(Ql[r + g + 8][k0 + tg + 4]);
#pragma unroll
            for (int nt = 0; nt < 4; nt++) {
                uint32_t kh0 = fb(Kh[nt * 8 + g][k0 + tg]);
                uint32_t kh1 = fb(Kh[nt * 8 + g][k0 + tg + 4]);
                uint32_t kl0 = fb(Kl[nt * 8 + g][k0 + tg]);
                uint32_t kl1 = fb(Kl[nt * 8 + g][k0 + tg + 4]);
                mma8(s[nt], qh_, kh0, kh1);
                mma8(s[nt], ql_, kh0, kh1);
                mma8(s[nt], qh_, kl0, kl1);
            }
        }

        // causal mask (only when this block can touch the diagonal)
        if (kt * 32 + 31 > qi * 128 + warp * 16) {
#pragma unroll
            for (int nt = 0; nt < 4; nt++)
#pragma unroll
                for (int c = 0; c < 4; c++) {
                    int key = kt * 32 + nt * 8 + 2 * tg + (c & 1);
                    int rr  = row0 + ((c & 2) ? 8 : 0);
                    if (key > rr) s[nt][c] = -1e30f;
                }
        }

        // online softmax (rows g and g+8)
#pragma unroll
        for (int r = 0; r < 2; r++) {
            const int cb = 2 * r;
            float mx = mr[r];
#pragma unroll
            for (int nt = 0; nt < 4; nt++)
                mx = fmaxf(mx, fmaxf(s[nt][cb], s[nt][cb + 1]));
            mx = fmaxf(mx, __shfl_xor_sync(0xffffffffu, mx, 1));
            mx = fmaxf(mx, __shfl_xor_sync(0xffffffffu, mx, 2));

            float alpha = __expf(mr[r] - mx);
            float rs = 0.f;
#pragma unroll
            for (int nt = 0; nt < 4; nt++) {
                float p0 = __expf(s[nt][cb] - mx);
                float p1 = __expf(s[nt][cb + 1] - mx);
                s[nt][cb] = p0; s[nt][cb + 1] = p1;
                rs += p0 + p1;
            }
            rs += __shfl_xor_sync(0xffffffffu, rs, 1);
            rs += __shfl_xor_sync(0xffffffffu, rs, 2);
            lsum[r] = lsum[r] * alpha + rs;
            mr[r]   = mx;
#pragma unroll
            for (int nt = 0; nt < 8; nt++) {
                o[nt][cb]     *= alpha;
                o[nt][cb + 1] *= alpha;
            }
        }

        // stage P (warp-private rows -> __syncwarp only)
#pragma unroll
        for (int nt = 0; nt < 4; nt++) {
            int col = nt * 8 + 2 * tg;
            Ps[warp * 16 + g][col]         = s[nt][0];
            Ps[warp * 16 + g][col + 1]     = s[nt][1];
            Ps[warp * 16 + g + 8][col]     = s[nt][2];
            Ps[warp * 16 + g + 8][col + 1] = s[nt][3];
        }
        __syncwarp();

        // O += P * V : 2xTF32 (P split, V rounded)
#pragma unroll
        for (int ks = 0; ks < 4; ks++) {
            const int k0 = ks * 8, r = warp * 16;
            uint32_t ah_[4], al_[4];
            split2(Ps[r + g][k0 + tg],         ah_[0], al_[0]);
            split2(Ps[r + g + 8][k0 + tg],     ah_[1], al_[1]);
            split2(Ps[r + g][k0 + tg + 4],     ah_[2], al_[2]);
            split2(Ps[r + g + 8][k0 + tg + 4], ah_[3], al_[3]);
#pragma unroll
            for (int nt = 0; nt < 8; nt++) {
                uint32_t v0 = fb(Vh[k0 + tg][nt * 8 + g]);
                uint32_t v1 = fb(Vh[k0 + tg + 4][nt * 8 + g]);
                mma8(o[nt], ah_, v0, v1);
                mma8(o[nt], al_, v0, v1);
            }
        }
    }

    // normalize + write [B, T, H*HS]
    const int bb = bh >> 4;
    const int hh = bh & 15;
    const float inv0 = 1.f / lsum[0];
    const float inv1 = 1.f / lsum[1];
#pragma unroll
    for (int nt = 0; nt < 8; nt++) {
        int col = hh * 64 + nt * 8 + 2 * tg;
        size_t a0 = (size_t)(bb * NT + row0) * NC + col;
        *(float2*)&g_attn[a0]          = make_float2(o[nt][0] * inv0, o[nt][1] * inv0);
        *(float2*)&g_attn[a0 + 8 * NC] = make_float2(o[nt][2] * inv1, o[nt][3] * inv1);
    }
}

// ---------------- launcher --------------------------------------------------
extern "C" void kernel_launch(void* const* d_in, const int* in_sizes, int n_in,
                              void* d_out, int out_size)
{
    const float* x  = (const float*)d_in[0];
    const float* Wq = (const float*)d_in[1];
    const float* Wk = (const float*)d_in[2];
    const float* Wv = (const float*)d_in[3];
    const float* Wo = (const float*)d_in[4];
    const float* bo = (const float*)d_in[5];
    float* out = (float*)d_out;

    const int smem_gemm  = 4 * 128 * 36 * 4;  // 73728 B
    const int smem_flash = (2 * 128 * 68 + 2 * 32 * 68 + 32 * 72 + 128 * 36) * 4;  // 114688 B

    cudaFuncSetAttribute(gemm_nt_kernel<0>, cudaFuncAttributeMaxDynamicSharedMemorySize, smem_gemm);
    cudaFuncSetAttribute(gemm_nt_kernel<1>, cudaFuncAttributeMaxDynamicSharedMemorySize, smem_gemm);
    cudaFuncSetAttribute(flash_attn_kernel, cudaFuncAttributeMaxDynamicSharedMemorySize, smem_flash);

    // 1) fused QKV projection -> g_q/g_k/g_v  [B,H,T,HS]
    gemm_nt_kernel<0><<<dim3(24, 64), 256, smem_gemm>>>(x, Wq, Wk, Wv, nullptr, nullptr);
    // 2) causal flash attention -> g_attn [B,T,C]
    flash_attn_kernel<<<dim3(NT / 128, NB * NH), 256, smem_flash>>>();
    // 3) output projection + bias -> d_out
    gemm_nt_kernel<1><<<dim3(8, 64), 256, smem_gemm>>>(nullptr, Wo, nullptr, nullptr, bo, out);
}

// round 5
// speedup vs baseline: 1.2310x; 1.2310x over previous
#include <cuda_runtime.h>
#include <cuda_bf16.h>
#include <cstdint>

#define NB 4
#define NT 2048
#define NC 1024
#define NH 16
#define NHS 64

// ---------------- scratch (static device globals) ---------------------------
__device__ float g_v[(size_t)NB * NH * NT * NHS];
__device__ __nv_bfloat16 g_qh[(size_t)NB * NH * NT * NHS];
__device__ __nv_bfloat16 g_ql[(size_t)NB * NH * NT * NHS];
__device__ __nv_bfloat16 g_kh[(size_t)NB * NH * NT * NHS];
__device__ __nv_bfloat16 g_kl[(size_t)NB * NH * NT * NHS];
__device__ __nv_bfloat16 g_xh[(size_t)NB * NT * NC];   // x split; reused for attn-out
__device__ __nv_bfloat16 g_xl[(size_t)NB * NT * NC];
__device__ __nv_bfloat16 g_wh[(size_t)3 * NC * NC];    // Wq|Wk|Wv rows concat
__device__ __nv_bfloat16 g_wl[(size_t)3 * NC * NC];
__device__ __nv_bfloat16 g_woh[(size_t)NC * NC];
__device__ __nv_bfloat16 g_wol[(size_t)NC * NC];

// ---------------- helpers ---------------------------------------------------
__device__ __forceinline__ void mma16(float* d, const uint32_t* a, uint32_t b0, uint32_t b1) {
    asm volatile(
        "mma.sync.aligned.m16n8k16.row.col.f32.bf16.bf16.f32 "
        "{%0,%1,%2,%3}, {%4,%5,%6,%7}, {%8,%9}, {%0,%1,%2,%3};"
        : "+f"(d[0]), "+f"(d[1]), "+f"(d[2]), "+f"(d[3])
        : "r"(a[0]), "r"(a[1]), "r"(a[2]), "r"(a[3]), "r"(b0), "r"(b1));
}
// split (a,b) -> packed bf16x2 hi + packed bf16x2 lo (a = lower index)
__device__ __forceinline__ void split_pack(float a, float b, uint32_t& h, uint32_t& l) {
    __nv_bfloat16 ha = __float2bfloat16(a), hb = __float2bfloat16(b);
    __nv_bfloat162 th; th.x = ha; th.y = hb;
    h = *(uint32_t*)&th;
    __nv_bfloat162 tl;
    tl.x = __float2bfloat16(a - __bfloat162float(ha));
    tl.y = __float2bfloat16(b - __bfloat162float(hb));
    l = *(uint32_t*)&tl;
}

// ---------------- split fp32 -> bf16 hi/lo (global) -------------------------
__global__ void __launch_bounds__(256) split_bf16_kernel(
    const float* __restrict__ src, __nv_bfloat16* __restrict__ dh, __nv_bfloat16* __restrict__ dl)
{
    int i = (blockIdx.x * 256 + threadIdx.x) * 4;
    float4 v = *(const float4*)(src + i);
    uint32_t h0, l0, h1, l1;
    split_pack(v.x, v.y, h0, l0);
    split_pack(v.z, v.w, h1, l1);
    *(uint32_t*)(dh + i) = h0; *(uint32_t*)(dh + i + 2) = h1;
    *(uint32_t*)(dl + i) = l0; *(uint32_t*)(dl + i + 2) = l1;
}

// ---------------- GEMM: C = A(Mx1024) * B(Nx1024)^T, 3xBF16 ----------------
// MODE 0: QKV. Epilogue scatters q (x8, bf16-split), k (bf16-split), v (f32).
// MODE 1: out projection + bias -> Out (f32).
// smem tiles in u32 (bf16x2) units, row stride 20 (16 data + 4 pad): banks
// (20g+tg)%32 distinct over the 8x4 fragment lanes.
template <int MODE>
__global__ void __launch_bounds__(256) gemm_bf16_kernel(
    const __nv_bfloat16* __restrict__ Ah, const __nv_bfloat16* __restrict__ Al,
    const __nv_bfloat16* __restrict__ Bh, const __nv_bfloat16* __restrict__ Bl,
    const float* __restrict__ bias, float* __restrict__ Out)
{
    extern __shared__ uint32_t su[];
    uint32_t* sAh = su;
    uint32_t* sAl = su + 2560;
    uint32_t* sBh = su + 5120;
    uint32_t* sBl = su + 7680;

    const int tid = threadIdx.x;
    const int warp = tid >> 5, lane = tid & 31;
    const int g = lane >> 2, tg = lane & 3;
    const int wm = warp >> 2, wn = warp & 3;      // 2x4 warps, warp tile 64x32
    const int m0 = blockIdx.y * 128;
    const int n0 = blockIdx.x * 128;              // B row base (0..3071 in MODE 0)

    float acc[4][4][4];
#pragma unroll
    for (int a = 0; a < 4; a++)
#pragma unroll
        for (int b = 0; b < 4; b++)
#pragma unroll
            for (int c = 0; c < 4; c++) acc[a][b][c] = 0.f;

    const int lr = tid >> 1;            // 0..127 (tile row)
    const int lc = (tid & 1) * 8;       // u32 col base 0 or 8

    uint4 rAh[2], rAl[2], rBh[2], rBl[2];
#define LD_TILES(KT)                                                                   \
    {                                                                                  \
        _Pragma("unroll") for (int j = 0; j < 2; j++) {                                \
            int eo = (KT) + (lc + 4 * j) * 2;                                          \
            rAh[j] = *(const uint4*)(Ah + (size_t)(m0 + lr) * NC + eo);                \
            rAl[j] = *(const uint4*)(Al + (size_t)(m0 + lr) * NC + eo);                \
            rBh[j] = *(const uint4*)(Bh + (size_t)(n0 + lr) * NC + eo);                \
            rBl[j] = *(const uint4*)(Bl + (size_t)(n0 + lr) * NC + eo);                \
        }                                                                              \
    }
    LD_TILES(0);

    for (int kt = 0; kt < NC; kt += 32) {
        __syncthreads();
#pragma unroll
        for (int j = 0; j < 2; j++) {
            int ci = lr * 20 + lc + 4 * j;
            *(uint4*)&sAh[ci] = rAh[j];
            *(uint4*)&sAl[ci] = rAl[j];
            *(uint4*)&sBh[ci] = rBh[j];
            *(uint4*)&sBl[ci] = rBl[j];
        }
        __syncthreads();
        if (kt + 32 < NC) LD_TILES(kt + 32);

#pragma unroll
        for (int ks = 0; ks < 2; ks++) {
            const int c0 = tg + 8 * ks;
            uint32_t ah[4][4], al[4][4];
#pragma unroll
            for (int mt = 0; mt < 4; mt++) {
                const int r = wm * 64 + mt * 16;
                ah[mt][0] = sAh[(r + g) * 20 + c0];     al[mt][0] = sAl[(r + g) * 20 + c0];
                ah[mt][1] = sAh[(r + g + 8) * 20 + c0]; al[mt][1] = sAl[(r + g + 8) * 20 + c0];
                ah[mt][2] = sAh[(r + g) * 20 + c0 + 4]; al[mt][2] = sAl[(r + g) * 20 + c0 + 4];
                ah[mt][3] = sAh[(r + g + 8) * 20 + c0 + 4];
                al[mt][3] = sAl[(r + g + 8) * 20 + c0 + 4];
            }
#pragma unroll
            for (int nt = 0; nt < 4; nt++) {
                const int cb = wn * 32 + nt * 8;
                uint32_t b0h = sBh[(cb + g) * 20 + c0];
                uint32_t b1h = sBh[(cb + g) * 20 + c0 + 4];
                uint32_t b0l = sBl[(cb + g) * 20 + c0];
                uint32_t b1l = sBl[(cb + g) * 20 + c0 + 4];
#pragma unroll
                for (int mt = 0; mt < 4; mt++) {
                    mma16(acc[mt][nt], ah[mt], b0h, b1h);
                    mma16(acc[mt][nt], al[mt], b0h, b1h);
                    mma16(acc[mt][nt], ah[mt], b0l, b1l);
                }
            }
        }
    }

    // epilogue
#pragma unroll
    for (int mt = 0; mt < 4; mt++) {
        int row = m0 + wm * 64 + mt * 16 + g;
#pragma unroll
        for (int nt = 0; nt < 4; nt++) {
            int colg = blockIdx.x * 128 + wn * 32 + nt * 8 + 2 * tg;
            if (MODE == 0) {
                int sel = colg >> 10, c = colg & 1023;
                int h = c >> 6, d = c & 63;
                int b = row >> 11, t = row & (NT - 1);
                size_t off = (((size_t)(b * NH + h) * NT) + t) * NHS + d;
                if (sel == 2) {
                    *(float2*)(g_v + off) = make_float2(acc[mt][nt][0], acc[mt][nt][1]);
                    *(float2*)(g_v + off + 8 * NHS) = make_float2(acc[mt][nt][2], acc[mt][nt][3]);
                } else {
                    float sc = (sel == 0) ? 8.f : 1.f;   // pre-scale Q by sqrt(HS)
                    __nv_bfloat16* dh = (sel == 0) ? g_qh : g_kh;
                    __nv_bfloat16* dl = (sel == 0) ? g_ql : g_kl;
                    uint32_t ph, pl;
                    split_pack(acc[mt][nt][0] * sc, acc[mt][nt][1] * sc, ph, pl);
                    *(uint32_t*)(dh + off) = ph;
                    *(uint32_t*)(dl + off) = pl;
                    split_pack(acc[mt][nt][2] * sc, acc[mt][nt][3] * sc, ph, pl);
                    *(uint32_t*)(dh + off + 8 * NHS) = ph;
                    *(uint32_t*)(dl + off + 8 * NHS) = pl;
                }
            } else {
                float2 bv = *(const float2*)(bias + colg);
                *(float2*)(Out + (size_t)row * NC + colg) =
                    make_float2(acc[mt][nt][0] + bv.x, acc[mt][nt][1] + bv.y);
                *(float2*)(Out + (size_t)(row + 8) * NC + colg) =
                    make_float2(acc[mt][nt][2] + bv.x, acc[mt][nt][3] + bv.y);
            }
        }
    }
}

// ---------------- flash attention (causal), 3xBF16 mma ----------------------
// Grid (T/128, B*H), 256 thr = 8 warps, warp w owns rows [16w,16w+16).
// Q/K pre-split bf16 (Q pre-scaled x8). V f32 -> split+transpose into swizzled
// [dim][key-pair] smem. Scores & PV: 3 bf16 passes (drop lo*lo).
__global__ void __launch_bounds__(256) flash_attn_kernel()
{
    extern __shared__ uint32_t su[];
    uint32_t* sQh = su;            // 128*36
    uint32_t* sQl = su + 4608;
    uint32_t* sKh = su + 9216;     // 32*36
    uint32_t* sKl = su + 10368;
    uint32_t* sVh = su + 11520;    // 64*20, col swizzled ^ (d>>3)&3
    uint32_t* sVl = su + 12800;
    uint32_t* sPh = su + 14080;    // 128*20
    uint32_t* sPl = su + 16640;    // total 19200 u32

    const int tid = threadIdx.x;
    const int warp = tid >> 5, lane = tid & 31;
    const int g = lane >> 2, tg = lane & 3;
    const int qi = blockIdx.x, bh = blockIdx.y;

    const size_t base = (size_t)bh * NT * NHS;
    const __nv_bfloat16* Qhg = g_qh + base + (size_t)qi * 128 * NHS;
    const __nv_bfloat16* Qlg = g_ql + base + (size_t)qi * 128 * NHS;
    const __nv_bfloat16* Khg = g_kh + base;
    const __nv_bfloat16* Klg = g_kl + base;
    const float* Vg = g_v + base;

    // load Q tile (bf16 pairs, already scaled)
    {
        int r = tid >> 1, cc = (tid & 1) * 16;
#pragma unroll
        for (int j = 0; j < 4; j++) {
            int eo = (cc + 4 * j) * 2;
            *(uint4*)&sQh[r * 36 + cc + 4 * j] = *(const uint4*)(Qhg + r * NHS + eo);
            *(uint4*)&sQl[r * 36 + cc + 4 * j] = *(const uint4*)(Qlg + r * NHS + eo);
        }
    }

    float o[8][4];
#pragma unroll
    for (int i = 0; i < 8; i++)
#pragma unroll
        for (int j = 0; j < 4; j++) o[i][j] = 0.f;
    float mr[2] = {-1e30f, -1e30f}, lsum[2] = {0.f, 0.f};

    const int row0 = qi * 128 + warp * 16 + g;
    const int nkt = 4 * qi + 4;

    const int kr = tid >> 3, kc = (tid & 7) * 4;   // K loader: row, u32 col
    const int vd = tid & 63, vq = tid >> 6;        // V loader: dim, quarter
    uint4 rkh, rkl;
    float rv0[4], rv1[4];
#define LD_KV(KT)                                                                  \
    {                                                                              \
        rkh = *(const uint4*)(Khg + (size_t)((KT) * 32 + kr) * NHS + kc * 2);      \
        rkl = *(const uint4*)(Klg + (size_t)((KT) * 32 + kr) * NHS + kc * 2);      \
        _Pragma("unroll") for (int i = 0; i < 4; i++) {                            \
            int kp = vq * 4 + i;                                                   \
            rv0[i] = Vg[(size_t)((KT) * 32 + 2 * kp) * NHS + vd];                  \
            rv1[i] = Vg[(size_t)((KT) * 32 + 2 * kp + 1) * NHS + vd];              \
        }                                                                          \
    }
    LD_KV(0);

    for (int kt = 0; kt < nkt; kt++) {
        __syncthreads();
        *(uint4*)&sKh[kr * 36 + kc] = rkh;
        *(uint4*)&sKl[kr * 36 + kc] = rkl;
        const int sw = (vd >> 3) & 3;
#pragma unroll
        for (int i = 0; i < 4; i++) {
            int kp = vq * 4 + i;
            uint32_t ph, pl;
            split_pack(rv0[i], rv1[i], ph, pl);
            sVh[vd * 20 + (kp ^ sw)] = ph;
            sVl[vd * 20 + (kp ^ sw)] = pl;
        }
        __syncthreads();
        if (kt + 1 < nkt) LD_KV(kt + 1);

        if (kt * 32 > qi * 128 + warp * 16 + 15) continue;  // fully masked

        // S = Q K^T (16x32 per warp)
        float s[4][4];
#pragma unroll
        for (int i = 0; i < 4; i++)
#pragma unroll
            for (int j = 0; j < 4; j++) s[i][j] = 0.f;

#pragma unroll
        for (int ks = 0; ks < 4; ks++) {
            const int c0 = tg + 8 * ks, r = warp * 16;
            uint32_t qh_[4], ql_[4];
            qh_[0] = sQh[(r + g) * 36 + c0];     ql_[0] = sQl[(r + g) * 36 + c0];
            qh_[1] = sQh[(r + g + 8) * 36 + c0]; ql_[1] = sQl[(r + g + 8) * 36 + c0];
            qh_[2] = sQh[(r + g) * 36 + c0 + 4]; ql_[2] = sQl[(r + g) * 36 + c0 + 4];
            qh_[3] = sQh[(r + g + 8) * 36 + c0 + 4];
            ql_[3] = sQl[(r + g + 8) * 36 + c0 + 4];
#pragma unroll
            for (int nt = 0; nt < 4; nt++) {
                uint32_t kh0 = sKh[(nt * 8 + g) * 36 + c0];
                uint32_t kh1 = sKh[(nt * 8 + g) * 36 + c0 + 4];
                uint32_t kl0 = sKl[(nt * 8 + g) * 36 + c0];
                uint32_t kl1 = sKl[(nt * 8 + g) * 36 + c0 + 4];
                mma16(s[nt], qh_, kh0, kh1);
                mma16(s[nt], ql_, kh0, kh1);
                mma16(s[nt], qh_, kl0, kl1);
            }
        }

        // causal mask
        if (kt * 32 + 31 > qi * 128 + warp * 16) {
#pragma unroll
            for (int nt = 0; nt < 4; nt++)
#pragma unroll
                for (int c = 0; c < 4; c++) {
                    int key = kt * 32 + nt * 8 + 2 * tg + (c & 1);
                    int rr = row0 + ((c & 2) ? 8 : 0);
                    if (key > rr) s[nt][c] = -1e30f;
                }
        }

        // online softmax (rows g, g+8)
#pragma unroll
        for (int r = 0; r < 2; r++) {
            const int cb = 2 * r;
            float mx = mr[r];
#pragma unroll
            for (int nt = 0; nt < 4; nt++)
                mx = fmaxf(mx, fmaxf(s[nt][cb], s[nt][cb + 1]));
            mx = fmaxf(mx, __shfl_xor_sync(0xffffffffu, mx, 1));
            mx = fmaxf(mx, __shfl_xor_sync(0xffffffffu, mx, 2));
            float alpha = __expf(mr[r] - mx);
            float rs = 0.f;
#pragma unroll
            for (int nt = 0; nt < 4; nt++) {
                float p0 = __expf(s[nt][cb] - mx);
                float p1 = __expf(s[nt][cb + 1] - mx);
                s[nt][cb] = p0; s[nt][cb + 1] = p1;
                rs += p0 + p1;
            }
            rs += __shfl_xor_sync(0xffffffffu, rs, 1);
            rs += __shfl_xor_sync(0xffffffffu, rs, 2);
            lsum[r] = lsum[r] * alpha + rs;
            mr[r] = mx;
#pragma unroll
            for (int nt = 0; nt < 8; nt++) {
                o[nt][cb] *= alpha; o[nt][cb + 1] *= alpha;
            }
        }

        // stage P split+packed (warp-private rows)
#pragma unroll
        for (int nt = 0; nt < 4; nt++) {
            uint32_t ph, pl;
            split_pack(s[nt][0], s[nt][1], ph, pl);
            sPh[(warp * 16 + g) * 20 + nt * 4 + tg] = ph;
            sPl[(warp * 16 + g) * 20 + nt * 4 + tg] = pl;
            split_pack(s[nt][2], s[nt][3], ph, pl);
            sPh[(warp * 16 + g + 8) * 20 + nt * 4 + tg] = ph;
            sPl[(warp * 16 + g + 8) * 20 + nt * 4 + tg] = pl;
        }
        __syncwarp();

        // O += P V
#pragma unroll
        for (int ks = 0; ks < 2; ks++) {
            const int c0 = tg + 8 * ks, r = warp * 16;
            uint32_t ah_[4], al_[4];
            ah_[0] = sPh[(r + g) * 20 + c0];     al_[0] = sPl[(r + g) * 20 + c0];
            ah_[1] = sPh[(r + g + 8) * 20 + c0]; al_[1] = sPl[(r + g + 8) * 20 + c0];
            ah_[2] = sPh[(r + g) * 20 + c0 + 4]; al_[2] = sPl[(r + g) * 20 + c0 + 4];
            ah_[3] = sPh[(r + g + 8) * 20 + c0 + 4];
            al_[3] = sPl[(r + g + 8) * 20 + c0 + 4];
#pragma unroll
            for (int nt = 0; nt < 8; nt++) {
                const int sz = nt & 3;
                uint32_t b0h = sVh[(nt * 8 + g) * 20 + (c0 ^ sz)];
                uint32_t b1h = sVh[(nt * 8 + g) * 20 + ((c0 + 4) ^ sz)];
                uint32_t b0l = sVl[(nt * 8 + g) * 20 + (c0 ^ sz)];
                uint32_t b1l = sVl[(nt * 8 + g) * 20 + ((c0 + 4) ^ sz)];
                mma16(o[nt], ah_, b0h, b1h);
                mma16(o[nt], al_, b0h, b1h);
                mma16(o[nt], ah_, b0l, b1l);
            }
        }
    }

    // normalize + write attn-out bf16-split into g_xh/g_xl [B,T,C]
    const int bb = bh >> 4, hh = bh & 15;
    const float inv0 = 1.f / lsum[0], inv1 = 1.f / lsum[1];
#pragma unroll
    for (int nt = 0; nt < 8; nt++) {
        int col = hh * 64 + nt * 8 + 2 * tg;
        size_t off = (size_t)(bb * NT + row0) * NC + col;
        uint32_t ph, pl;
        split_pack(o[nt][0] * inv0, o[nt][1] * inv0, ph, pl);
        *(uint32_t*)(g_xh + off) = ph;
        *(uint32_t*)(g_xl + off) = pl;
        split_pack(o[nt][2] * inv1, o[nt][3] * inv1, ph, pl);
        *(uint32_t*)(g_xh + off + 8 * NC) = ph;
        *(uint32_t*)(g_xl + off + 8 * NC) = pl;
    }
}

// ---------------- launcher --------------------------------------------------
extern "C" void kernel_launch(void* const* d_in, const int* in_sizes, int n_in,
                              void* d_out, int out_size)
{
    const float* x  = (const float*)d_in[0];
    const float* Wq = (const float*)d_in[1];
    const float* Wk = (const float*)d_in[2];
    const float* Wv = (const float*)d_in[3];
    const float* Wo = (const float*)d_in[4];
    const float* bo = (const float*)d_in[5];
    float* out = (float*)d_out;

    void *p_xh, *p_xl, *p_wh, *p_wl, *p_woh, *p_wol;
    cudaGetSymbolAddress(&p_xh, g_xh);   cudaGetSymbolAddress(&p_xl, g_xl);
    cudaGetSymbolAddress(&p_wh, g_wh);   cudaGetSymbolAddress(&p_wl, g_wl);
    cudaGetSymbolAddress(&p_woh, g_woh); cudaGetSymbolAddress(&p_wol, g_wol);

    __nv_bfloat16* xh = (__nv_bfloat16*)p_xh;
    __nv_bfloat16* xl = (__nv_bfloat16*)p_xl;
    __nv_bfloat16* wh = (__nv_bfloat16*)p_wh;
    __nv_bfloat16* wl = (__nv_bfloat16*)p_wl;

    const int smem_gemm  = 10240 * 4;   // 40 KB
    const int smem_flash = 19200 * 4;   // 75 KB
    cudaFuncSetAttribute(gemm_bf16_kernel<0>, cudaFuncAttributeMaxDynamicSharedMemorySize, smem_gemm);
    cudaFuncSetAttribute(gemm_bf16_kernel<1>, cudaFuncAttributeMaxDynamicSharedMemorySize, smem_gemm);
    cudaFuncSetAttribute(flash_attn_kernel, cudaFuncAttributeMaxDynamicSharedMemorySize, smem_flash);

    // 1) pre-split inputs/weights
    split_bf16_kernel<<<8192, 256>>>(x, xh, xl);
    split_bf16_kernel<<<1024, 256>>>(Wq, wh, wl);
    split_bf16_kernel<<<1024, 256>>>(Wk, wh + (size_t)NC * NC, wl + (size_t)NC * NC);
    split_bf16_kernel<<<1024, 256>>>(Wv, wh + (size_t)2 * NC * NC, wl + (size_t)2 * NC * NC);
    split_bf16_kernel<<<1024, 256>>>(Wo, (__nv_bfloat16*)p_woh, (__nv_bfloat16*)p_wol);

    // 2) QKV projection -> g_qh/ql, g_kh/kl (bf16-split), g_v (f32)
    gemm_bf16_kernel<0><<<dim3(24, 64), 256, smem_gemm>>>(
        xh, xl, wh, wl, nullptr, nullptr);

    // 3) causal flash attention -> g_xh/g_xl (attn out, bf16-split)
    flash_attn_kernel<<<dim3(NT / 128, NB * NH), 256, smem_flash>>>();

    // 4) out projection + bias -> d_out
    gemm_bf16_kernel<1><<<dim3(8, 64), 256, smem_gemm>>>(
        xh, xl, (__nv_bfloat16*)p_woh, (__nv_bfloat16*)p_wol, bo, out);
}

// round 6
// speedup vs baseline: 1.4631x; 1.1886x over previous
#include <cuda_runtime.h>
#include <cuda_bf16.h>
#include <cstdint>

#define NB 4
#define NT 2048
#define NC 1024
#define NH 16
#define NHS 64

// ---------------- scratch (static device globals) ---------------------------
__device__ float g_v[(size_t)NB * NH * NT * NHS];
__device__ __nv_bfloat16 g_qh[(size_t)NB * NH * NT * NHS];
__device__ __nv_bfloat16 g_ql[(size_t)NB * NH * NT * NHS];
__device__ __nv_bfloat16 g_kh[(size_t)NB * NH * NT * NHS];
__device__ __nv_bfloat16 g_kl[(size_t)NB * NH * NT * NHS];
__device__ __nv_bfloat16 g_xh[(size_t)NB * NT * NC];   // x split; reused for attn-out
__device__ __nv_bfloat16 g_xl[(size_t)NB * NT * NC];
__device__ __nv_bfloat16 g_wh[(size_t)3 * NC * NC];    // Wq|Wk|Wv rows concat
__device__ __nv_bfloat16 g_wl[(size_t)3 * NC * NC];
__device__ __nv_bfloat16 g_woh[(size_t)NC * NC];
__device__ __nv_bfloat16 g_wol[(size_t)NC * NC];

// ---------------- helpers ---------------------------------------------------
__device__ __forceinline__ void mma16(float* d, const uint32_t* a, uint32_t b0, uint32_t b1) {
    asm volatile(
        "mma.sync.aligned.m16n8k16.row.col.f32.bf16.bf16.f32 "
        "{%0,%1,%2,%3}, {%4,%5,%6,%7}, {%8,%9}, {%0,%1,%2,%3};"
        : "+f"(d[0]), "+f"(d[1]), "+f"(d[2]), "+f"(d[3])
        : "r"(a[0]), "r"(a[1]), "r"(a[2]), "r"(a[3]), "r"(b0), "r"(b1));
}
__device__ __forceinline__ void split_pack(float a, float b, uint32_t& h, uint32_t& l) {
    __nv_bfloat16 ha = __float2bfloat16(a), hb = __float2bfloat16(b);
    __nv_bfloat162 th; th.x = ha; th.y = hb;
    h = *(uint32_t*)&th;
    __nv_bfloat162 tl;
    tl.x = __float2bfloat16(a - __bfloat162float(ha));
    tl.y = __float2bfloat16(b - __bfloat162float(hb));
    l = *(uint32_t*)&tl;
}
#define CPA16(dst, src) \
    asm volatile("cp.async.cg.shared.global [%0], [%1], 16;" :: "r"(dst), "l"(src))
#define CPA_COMMIT() asm volatile("cp.async.commit_group;" ::: "memory")
#define CPA_WAIT1() asm volatile("cp.async.wait_group 1;" ::: "memory")
#define CPA_WAIT0() asm volatile("cp.async.wait_group 0;" ::: "memory")

// ---------------- fused split: fp32 -> bf16 hi/lo for all 5 tensors ---------
__global__ void __launch_bounds__(256) split_all_kernel(
    const float* __restrict__ x,  const float* __restrict__ Wq,
    const float* __restrict__ Wk, const float* __restrict__ Wv,
    const float* __restrict__ Wo)
{
    const size_t XN = (size_t)NB * NT * NC;   // 8M
    const size_t WN = (size_t)NC * NC;        // 1M
    size_t i = ((size_t)blockIdx.x * 256 + threadIdx.x) * 4;
    const float* src;
    __nv_bfloat16 *dh, *dl;
    size_t off;
    if (i < XN)               { src = x;  dh = g_xh;          dl = g_xl;          off = i; }
    else if (i < XN + WN)     { src = Wq; dh = g_wh;          dl = g_wl;          off = i - XN; }
    else if (i < XN + 2 * WN) { src = Wk; dh = g_wh + WN;     dl = g_wl + WN;     off = i - XN - WN; }
    else if (i < XN + 3 * WN) { src = Wv; dh = g_wh + 2 * WN; dl = g_wl + 2 * WN; off = i - XN - 2 * WN; }
    else                      { src = Wo; dh = g_woh;         dl = g_wol;         off = i - XN - 3 * WN; }
    float4 v = *(const float4*)(src + off);
    uint32_t h0, l0, h1, l1;
    split_pack(v.x, v.y, h0, l0);
    split_pack(v.z, v.w, h1, l1);
    *(uint32_t*)(dh + off) = h0; *(uint32_t*)(dh + off + 2) = h1;
    *(uint32_t*)(dl + off) = l0; *(uint32_t*)(dl + off + 2) = l1;
}

// ---------------- GEMM: C = A(Mx1024) * B(Nx1024)^T, 3xBF16 ----------------
// cp.async 2-stage pipeline, 128x128 tile, K-chunk 32.
// MODE 0: A=x split, B=Wqkv split; scatter q (x8, split) / k (split) / v (f32).
// MODE 1: A=attn split, B=Wo split; Out = C + bias (f32).
// smem u32 units, row stride 20 (16 data + 4 pad).
static constexpr int G_STG = 10240;  // u32 per stage (4 arrays x 128 x 20)
static constexpr int GEMM_SMEM = 2 * G_STG * 4;  // 81920 B

template <int MODE>
__global__ void __launch_bounds__(256, 2) gemm_bf16_kernel(
    const float* __restrict__ bias, float* __restrict__ Out)
{
    extern __shared__ uint32_t su[];

    const int tid = threadIdx.x;
    const int warp = tid >> 5, lane = tid & 31;
    const int g = lane >> 2, tg = lane & 3;
    const int wm = warp >> 2, wn = warp & 3;      // 2x4 warps, warp tile 64x32
    const int m0 = blockIdx.y * 128;
    const int n0 = blockIdx.x * 128;

    const __nv_bfloat16* Ah = g_xh;
    const __nv_bfloat16* Al = g_xl;
    const __nv_bfloat16* Bh = (MODE == 0) ? g_wh : g_woh;
    const __nv_bfloat16* Bl = (MODE == 0) ? g_wl : g_wol;

    float acc[4][4][4];
#pragma unroll
    for (int a = 0; a < 4; a++)
#pragma unroll
        for (int b = 0; b < 4; b++)
#pragma unroll
            for (int c = 0; c < 4; c++) acc[a][b][c] = 0.f;

    const int lr = tid >> 1;            // 0..127 (tile row)
    const int lc = (tid & 1) * 8;       // u32 col base 0 or 8
    const __nv_bfloat16* pA_h = Ah + (size_t)(m0 + lr) * NC + lc * 2;
    const __nv_bfloat16* pA_l = Al + (size_t)(m0 + lr) * NC + lc * 2;
    const __nv_bfloat16* pB_h = Bh + (size_t)(n0 + lr) * NC + lc * 2;
    const __nv_bfloat16* pB_l = Bl + (size_t)(n0 + lr) * NC + lc * 2;
    const uint32_t sdst = (uint32_t)__cvta_generic_to_shared(su + lr * 20 + lc);

#define G_LOAD(S, KT)                                                          \
    {                                                                          \
        uint32_t d0 = sdst + (S) * (G_STG * 4);                                \
        CPA16(d0,                 pA_h + (KT));                                \
        CPA16(d0 + 16,            pA_h + (KT) + 8);                            \
        CPA16(d0 + 2560 * 4,      pA_l + (KT));                                \
        CPA16(d0 + 2560 * 4 + 16, pA_l + (KT) + 8);                            \
        CPA16(d0 + 5120 * 4,      pB_h + (KT));                                \
        CPA16(d0 + 5120 * 4 + 16, pB_h + (KT) + 8);                            \
        CPA16(d0 + 7680 * 4,      pB_l + (KT));                                \
        CPA16(d0 + 7680 * 4 + 16, pB_l + (KT) + 8);                            \
        CPA_COMMIT();                                                          \
    }

    G_LOAD(0, 0);

    for (int c = 0; c < 32; c++) {
        if (c < 31) { G_LOAD((c + 1) & 1, (c + 1) * 32); CPA_WAIT1(); }
        else        { CPA_WAIT0(); }
        __syncthreads();

        const uint32_t* sAh = su + (c & 1) * G_STG;
        const uint32_t* sAl = sAh + 2560;
        const uint32_t* sBh = sAh + 5120;
        const uint32_t* sBl = sAh + 7680;

#pragma unroll
        for (int ks = 0; ks < 2; ks++) {
            const int c0 = tg + 8 * ks;
            uint32_t ah[4][4], al[4][4];
#pragma unroll
            for (int mt = 0; mt < 4; mt++) {
                const int r = wm * 64 + mt * 16;
                ah[mt][0] = sAh[(r + g) * 20 + c0];     al[mt][0] = sAl[(r + g) * 20 + c0];
                ah[mt][1] = sAh[(r + g + 8) * 20 + c0]; al[mt][1] = sAl[(r + g + 8) * 20 + c0];
                ah[mt][2] = sAh[(r + g) * 20 + c0 + 4]; al[mt][2] = sAl[(r + g) * 20 + c0 + 4];
                ah[mt][3] = sAh[(r + g + 8) * 20 + c0 + 4];
                al[mt][3] = sAl[(r + g + 8) * 20 + c0 + 4];
            }
#pragma unroll
            for (int nt = 0; nt < 4; nt++) {
                const int cb = wn * 32 + nt * 8;
                uint32_t b0h = sBh[(cb + g) * 20 + c0];
                uint32_t b1h = sBh[(cb + g) * 20 + c0 + 4];
                uint32_t b0l = sBl[(cb + g) * 20 + c0];
                uint32_t b1l = sBl[(cb + g) * 20 + c0 + 4];
#pragma unroll
                for (int mt = 0; mt < 4; mt++) {
                    mma16(acc[mt][nt], ah[mt], b0h, b1h);
                    mma16(acc[mt][nt], al[mt], b0h, b1h);
                    mma16(acc[mt][nt], ah[mt], b0l, b1l);
                }
            }
        }
        __syncthreads();
    }

    // epilogue
#pragma unroll
    for (int mt = 0; mt < 4; mt++) {
        int row = m0 + wm * 64 + mt * 16 + g;
#pragma unroll
        for (int nt = 0; nt < 4; nt++) {
            int colg = blockIdx.x * 128 + wn * 32 + nt * 8 + 2 * tg;
            if (MODE == 0) {
                int sel = colg >> 10, c = colg & 1023;
                int h = c >> 6, d = c & 63;
                int b = row >> 11, t = row & (NT - 1);
                size_t off = (((size_t)(b * NH + h) * NT) + t) * NHS + d;
                if (sel == 2) {
                    *(float2*)(g_v + off) = make_float2(acc[mt][nt][0], acc[mt][nt][1]);
                    *(float2*)(g_v + off + 8 * NHS) = make_float2(acc[mt][nt][2], acc[mt][nt][3]);
                } else {
                    float sc = (sel == 0) ? 8.f : 1.f;   // pre-scale Q by sqrt(HS)
                    __nv_bfloat16* dh = (sel == 0) ? g_qh : g_kh;
                    __nv_bfloat16* dl = (sel == 0) ? g_ql : g_kl;
                    uint32_t ph, pl;
                    split_pack(acc[mt][nt][0] * sc, acc[mt][nt][1] * sc, ph, pl);
                    *(uint32_t*)(dh + off) = ph;
                    *(uint32_t*)(dl + off) = pl;
                    split_pack(acc[mt][nt][2] * sc, acc[mt][nt][3] * sc, ph, pl);
                    *(uint32_t*)(dh + off + 8 * NHS) = ph;
                    *(uint32_t*)(dl + off + 8 * NHS) = pl;
                }
            } else {
                float2 bv = *(const float2*)(bias + colg);
                *(float2*)(Out + (size_t)row * NC + colg) =
                    make_float2(acc[mt][nt][0] + bv.x, acc[mt][nt][1] + bv.y);
                *(float2*)(Out + (size_t)(row + 8) * NC + colg) =
                    make_float2(acc[mt][nt][2] + bv.x, acc[mt][nt][3] + bv.y);
            }
        }
    }
}

// ---------------- flash attention (causal), 3xBF16 mma ----------------------
// Grid (T/128, B*H), 256 thr = 8 warps, warp w owns rows [16w,16w+16).
// qi order reversed so longest CTAs launch first.
__global__ void __launch_bounds__(256, 2) flash_attn_kernel()
{
    extern __shared__ uint32_t su[];
    uint32_t* sQh = su;            // 128*36
    uint32_t* sQl = su + 4608;
    uint32_t* sKh = su + 9216;     // 32*36
    uint32_t* sKl = su + 10368;
    uint32_t* sVh = su + 11520;    // 64*20, col swizzled ^ (d>>3)&3
    uint32_t* sVl = su + 12800;
    uint32_t* sPh = su + 14080;    // 128*20
    uint32_t* sPl = su + 16640;    // total 19200 u32

    const int tid = threadIdx.x;
    const int warp = tid >> 5, lane = tid & 31;
    const int g = lane >> 2, tg = lane & 3;
    const int qi = (int)gridDim.x - 1 - (int)blockIdx.x;   // longest first
    const int bh = blockIdx.y;

    const size_t base = (size_t)bh * NT * NHS;
    const __nv_bfloat16* Qhg = g_qh + base + (size_t)qi * 128 * NHS;
    const __nv_bfloat16* Qlg = g_ql + base + (size_t)qi * 128 * NHS;
    const __nv_bfloat16* Khg = g_kh + base;
    const __nv_bfloat16* Klg = g_kl + base;
    const float* Vg = g_v + base;

    // load Q tile (bf16 pairs, already scaled)
    {
        int r = tid >> 1, cc = (tid & 1) * 16;
#pragma unroll
        for (int j = 0; j < 4; j++) {
            int eo = (cc + 4 * j) * 2;
            *(uint4*)&sQh[r * 36 + cc + 4 * j] = *(const uint4*)(Qhg + r * NHS + eo);
            *(uint4*)&sQl[r * 36 + cc + 4 * j] = *(const uint4*)(Qlg + r * NHS + eo);
        }
    }

    float o[8][4];
#pragma unroll
    for (int i = 0; i < 8; i++)
#pragma unroll
        for (int j = 0; j < 4; j++) o[i][j] = 0.f;
    float mr[2] = {-1e30f, -1e30f}, lsum[2] = {0.f, 0.f};

    const int row0 = qi * 128 + warp * 16 + g;
    const int nkt = 4 * qi + 4;

    const int kr = tid >> 3, kc = (tid & 7) * 4;   // K loader: row, u32 col
    const int vd = tid & 63, vq = tid >> 6;        // V loader: dim, quarter
    uint4 rkh, rkl;
    float rv0[4], rv1[4];
#define LD_KV(KT)                                                                  \
    {                                                                              \
        rkh = *(const uint4*)(Khg + (size_t)((KT) * 32 + kr) * NHS + kc * 2);      \
        rkl = *(const uint4*)(Klg + (size_t)((KT) * 32 + kr) * NHS + kc * 2);      \
        _Pragma("unroll") for (int i = 0; i < 4; i++) {                            \
            int kp = vq * 4 + i;                                                   \
            rv0[i] = Vg[(size_t)((KT) * 32 + 2 * kp) * NHS + vd];                  \
            rv1[i] = Vg[(size_t)((KT) * 32 + 2 * kp + 1) * NHS + vd];              \
        }                                                                          \
    }
    LD_KV(0);

    for (int kt = 0; kt < nkt; kt++) {
        __syncthreads();
        *(uint4*)&sKh[kr * 36 + kc] = rkh;
        *(uint4*)&sKl[kr * 36 + kc] = rkl;
        const int sw = (vd >> 3) & 3;
#pragma unroll
        for (int i = 0; i < 4; i++) {
            int kp = vq * 4 + i;
            uint32_t ph, pl;
            split_pack(rv0[i], rv1[i], ph, pl);
            sVh[vd * 20 + (kp ^ sw)] = ph;
            sVl[vd * 20 + (kp ^ sw)] = pl;
        }
        __syncthreads();
        if (kt + 1 < nkt) LD_KV(kt + 1);

        if (kt * 32 > qi * 128 + warp * 16 + 15) continue;  // fully masked

        // S = Q K^T (16x32 per warp)
        float s[4][4];
#pragma unroll
        for (int i = 0; i < 4; i++)
#pragma unroll
            for (int j = 0; j < 4; j++) s[i][j] = 0.f;

#pragma unroll
        for (int ks = 0; ks < 4; ks++) {
            const int c0 = tg + 8 * ks, r = warp * 16;
            uint32_t qh_[4], ql_[4];
            qh_[0] = sQh[(r + g) * 36 + c0];     ql_[0] = sQl[(r + g) * 36 + c0];
            qh_[1] = sQh[(r + g + 8) * 36 + c0]; ql_[1] = sQl[(r + g + 8) * 36 + c0];
            qh_[2] = sQh[(r + g) * 36 + c0 + 4]; ql_[2] = sQl[(r + g) * 36 + c0 + 4];
            qh_[3] = sQh[(r + g + 8) * 36 + c0 + 4];
            ql_[3] = sQl[(r + g + 8) * 36 + c0 + 4];
#pragma unroll
            for (int nt = 0; nt < 4; nt++) {
                uint32_t kh0 = sKh[(nt * 8 + g) * 36 + c0];
                uint32_t kh1 = sKh[(nt * 8 + g) * 36 + c0 + 4];
                uint32_t kl0 = sKl[(nt * 8 + g) * 36 + c0];
                uint32_t kl1 = sKl[(nt * 8 + g) * 36 + c0 + 4];
                mma16(s[nt], qh_, kh0, kh1);
                mma16(s[nt], ql_, kh0, kh1);
                mma16(s[nt], qh_, kl0, kl1);
            }
        }

        // causal mask
        if (kt * 32 + 31 > qi * 128 + warp * 16) {
#pragma unroll
            for (int nt = 0; nt < 4; nt++)
#pragma unroll
                for (int c = 0; c < 4; c++) {
                    int key = kt * 32 + nt * 8 + 2 * tg + (c & 1);
                    int rr = row0 + ((c & 2) ? 8 : 0);
                    if (key > rr) s[nt][c] = -1e30f;
                }
        }

        // online softmax (rows g, g+8)
#pragma unroll
        for (int r = 0; r < 2; r++) {
            const int cb = 2 * r;
            float mx = mr[r];
#pragma unroll
            for (int nt = 0; nt < 4; nt++)
                mx = fmaxf(mx, fmaxf(s[nt][cb], s[nt][cb + 1]));
            mx = fmaxf(mx, __shfl_xor_sync(0xffffffffu, mx, 1));
            mx = fmaxf(mx, __shfl_xor_sync(0xffffffffu, mx, 2));
            float alpha = __expf(mr[r] - mx);
            float rs = 0.f;
#pragma unroll
            for (int nt = 0; nt < 4; nt++) {
                float p0 = __expf(s[nt][cb] - mx);
                float p1 = __expf(s[nt][cb + 1] - mx);
                s[nt][cb] = p0; s[nt][cb + 1] = p1;
                rs += p0 + p1;
            }
            rs += __shfl_xor_sync(0xffffffffu, rs, 1);
            rs += __shfl_xor_sync(0xffffffffu, rs, 2);
            lsum[r] = lsum[r] * alpha + rs;
            mr[r] = mx;
#pragma unroll
            for (int nt = 0; nt < 8; nt++) {
                o[nt][cb] *= alpha; o[nt][cb + 1] *= alpha;
            }
        }

        // stage P split+packed (warp-private rows)
#pragma unroll
        for (int nt = 0; nt < 4; nt++) {
            uint32_t ph, pl;
            split_pack(s[nt][0], s[nt][1], ph, pl);
            sPh[(warp * 16 + g) * 20 + nt * 4 + tg] = ph;
            sPl[(warp * 16 + g) * 20 + nt * 4 + tg] = pl;
            split_pack(s[nt][2], s[nt][3], ph, pl);
            sPh[(warp * 16 + g + 8) * 20 + nt * 4 + tg] = ph;
            sPl[(warp * 16 + g + 8) * 20 + nt * 4 + tg] = pl;
        }
        __syncwarp();

        // O += P V
#pragma unroll
        for (int ks = 0; ks < 2; ks++) {
            const int c0 = tg + 8 * ks, r = warp * 16;
            uint32_t ah_[4], al_[4];
            ah_[0] = sPh[(r + g) * 20 + c0];     al_[0] = sPl[(r + g) * 20 + c0];
            ah_[1] = sPh[(r + g + 8) * 20 + c0]; al_[1] = sPl[(r + g + 8) * 20 + c0];
            ah_[2] = sPh[(r + g) * 20 + c0 + 4]; al_[2] = sPl[(r + g) * 20 + c0 + 4];
            ah_[3] = sPh[(r + g + 8) * 20 + c0 + 4];
            al_[3] = sPl[(r + g + 8) * 20 + c0 + 4];
#pragma unroll
            for (int nt = 0; nt < 8; nt++) {
                const int sz = nt & 3;
                uint32_t b0h = sVh[(nt * 8 + g) * 20 + (c0 ^ sz)];
                uint32_t b1h = sVh[(nt * 8 + g) * 20 + ((c0 + 4) ^ sz)];
                uint32_t b0l = sVl[(nt * 8 + g) * 20 + (c0 ^ sz)];
                uint32_t b1l = sVl[(nt * 8 + g) * 20 + ((c0 + 4) ^ sz)];
                mma16(o[nt], ah_, b0h, b1h);
                mma16(o[nt], al_, b0h, b1h);
                mma16(o[nt], ah_, b0l, b1l);
            }
        }
    }

    // normalize + write attn-out bf16-split into g_xh/g_xl [B,T,C]
    const int bb = bh >> 4, hh = bh & 15;
    const float inv0 = 1.f / lsum[0], inv1 = 1.f / lsum[1];
#pragma unroll
    for (int nt = 0; nt < 8; nt++) {
        int col = hh * 64 + nt * 8 + 2 * tg;
        size_t off = (size_t)(bb * NT + row0) * NC + col;
        uint32_t ph, pl;
        split_pack(o[nt][0] * inv0, o[nt][1] * inv0, ph, pl);
        *(uint32_t*)(g_xh + off) = ph;
        *(uint32_t*)(g_xl + off) = pl;
        split_pack(o[nt][2] * inv1, o[nt][3] * inv1, ph, pl);
        *(uint32_t*)(g_xh + off + 8 * NC) = ph;
        *(uint32_t*)(g_xl + off + 8 * NC) = pl;
    }
}

// ---------------- launcher --------------------------------------------------
extern "C" void kernel_launch(void* const* d_in, const int* in_sizes, int n_in,
                              void* d_out, int out_size)
{
    const float* x  = (const float*)d_in[0];
    const float* Wq = (const float*)d_in[1];
    const float* Wk = (const float*)d_in[2];
    const float* Wv = (const float*)d_in[3];
    const float* Wo = (const float*)d_in[4];
    const float* bo = (const float*)d_in[5];
    float* out = (float*)d_out;

    const int smem_flash = 19200 * 4;   // 75 KB
    cudaFuncSetAttribute(gemm_bf16_kernel<0>, cudaFuncAttributeMaxDynamicSharedMemorySize, GEMM_SMEM);
    cudaFuncSetAttribute(gemm_bf16_kernel<1>, cudaFuncAttributeMaxDynamicSharedMemorySize, GEMM_SMEM);
    cudaFuncSetAttribute(flash_attn_kernel, cudaFuncAttributeMaxDynamicSharedMemorySize, smem_flash);

    // 1) pre-split x + all weights to bf16 hi/lo (one fused launch)
    //    total elements = 8M (x) + 4M (Wq,Wk,Wv,Wo) = 12M; 4 per thread.
    split_all_kernel<<<12288, 256>>>(x, Wq, Wk, Wv, Wo);

    // 2) QKV projection -> g_qh/ql, g_kh/kl (bf16-split), g_v (f32)
    gemm_bf16_kernel<0><<<dim3(24, 64), 256, GEMM_SMEM>>>(nullptr, nullptr);

    // 3) causal flash attention -> g_xh/g_xl (attn out, bf16-split)
    flash_attn_kernel<<<dim3(NT / 128, NB * NH), 256, smem_flash>>>();

    // 4) out projection + bias -> d_out
    gemm_bf16_kernel<1><<<dim3(8, 64), 256, GEMM_SMEM>>>(bo, out);
}

// round 9
// speedup vs baseline: 1.5625x; 1.0679x over previous
#include <cuda_runtime.h>
#include <cuda_bf16.h>
#include <cstdint>

#define NB 4
#define NT 2048
#define NC 1024
#define NH 16
#define NHS 64

// ---------------- scratch (static device globals) ---------------------------
__device__ float g_v[(size_t)NB * NH * NT * NHS];
__device__ __nv_bfloat16 g_qh[(size_t)NB * NH * NT * NHS];
__device__ __nv_bfloat16 g_ql[(size_t)NB * NH * NT * NHS];
__device__ __nv_bfloat16 g_kh[(size_t)NB * NH * NT * NHS];
__device__ __nv_bfloat16 g_kl[(size_t)NB * NH * NT * NHS];
__device__ __nv_bfloat16 g_xh[(size_t)NB * NT * NC];   // x split; reused for attn-out
__device__ __nv_bfloat16 g_xl[(size_t)NB * NT * NC];
__device__ __nv_bfloat16 g_wh[(size_t)3 * NC * NC];    // Wq|Wk|Wv rows concat
__device__ __nv_bfloat16 g_wl[(size_t)3 * NC * NC];
__device__ __nv_bfloat16 g_woh[(size_t)NC * NC];
__device__ __nv_bfloat16 g_wol[(size_t)NC * NC];

// ---------------- helpers ---------------------------------------------------
__device__ __forceinline__ void mma16(float* d, const uint32_t* a, uint32_t b0, uint32_t b1) {
    asm volatile(
        "mma.sync.aligned.m16n8k16.row.col.f32.bf16.bf16.f32 "
        "{%0,%1,%2,%3}, {%4,%5,%6,%7}, {%8,%9}, {%0,%1,%2,%3};"
        : "+f"(d[0]), "+f"(d[1]), "+f"(d[2]), "+f"(d[3])
        : "r"(a[0]), "r"(a[1]), "r"(a[2]), "r"(a[3]), "r"(b0), "r"(b1));
}
__device__ __forceinline__ void ldsm4(uint32_t* r, uint32_t addr) {
    asm volatile("ldmatrix.sync.aligned.m8n8.x4.shared.b16 {%0,%1,%2,%3}, [%4];"
                 : "=r"(r[0]), "=r"(r[1]), "=r"(r[2]), "=r"(r[3]) : "r"(addr));
}
__device__ __forceinline__ void split_pack(float a, float b, uint32_t& h, uint32_t& l) {
    __nv_bfloat16 ha = __float2bfloat16(a), hb = __float2bfloat16(b);
    __nv_bfloat162 th; th.x = ha; th.y = hb;
    h = *(uint32_t*)&th;
    __nv_bfloat162 tl;
    tl.x = __float2bfloat16(a - __bfloat162float(ha));
    tl.y = __float2bfloat16(b - __bfloat162float(hb));
    l = *(uint32_t*)&tl;
}
#define CPA16(dst, src) \
    asm volatile("cp.async.cg.shared.global [%0], [%1], 16;" :: "r"(dst), "l"(src))
#define CPA_COMMIT() asm volatile("cp.async.commit_group;" ::: "memory")
#define CPA_WAIT1() asm volatile("cp.async.wait_group 1;" ::: "memory")
#define CPA_WAIT0() asm volatile("cp.async.wait_group 0;" ::: "memory")

// ---------------- fused split: fp32 -> bf16 hi/lo for all 5 tensors ---------
__global__ void __launch_bounds__(256) split_all_kernel(
    const float* __restrict__ x,  const float* __restrict__ Wq,
    const float* __restrict__ Wk, const float* __restrict__ Wv,
    const float* __restrict__ Wo)
{
    const size_t XN = (size_t)NB * NT * NC;   // 8M
    const size_t WN = (size_t)NC * NC;        // 1M
    size_t i = ((size_t)blockIdx.x * 256 + threadIdx.x) * 4;
    const float* src;
    __nv_bfloat16 *dh, *dl;
    size_t off;
    if (i < XN)               { src = x;  dh = g_xh;          dl = g_xl;          off = i; }
    else if (i < XN + WN)     { src = Wq; dh = g_wh;          dl = g_wl;          off = i - XN; }
    else if (i < XN + 2 * WN) { src = Wk; dh = g_wh + WN;     dl = g_wl + WN;     off = i - XN - WN; }
    else if (i < XN + 3 * WN) { src = Wv; dh = g_wh + 2 * WN; dl = g_wl + 2 * WN; off = i - XN - 2 * WN; }
    else                      { src = Wo; dh = g_woh;         dl = g_wol;         off = i - XN - 3 * WN; }
    float4 v = *(const float4*)(src + off);
    uint32_t h0, l0, h1, l1;
    split_pack(v.x, v.y, h0, l0);
    split_pack(v.z, v.w, h1, l1);
    *(uint32_t*)(dh + off) = h0; *(uint32_t*)(dh + off + 2) = h1;
    *(uint32_t*)(dl + off) = l0; *(uint32_t*)(dl + off + 2) = l1;
}

// ---------------- GEMM: C = A(Mx1024) * B(Nx1024)^T, 3xBF16 ----------------
// cp.async 2-stage pipeline + ldmatrix fragment loads. 128x128 tile, K-chunk 32.
static constexpr int G_STG = 10240;  // u32 per stage (4 arrays x 128 x 20)
static constexpr int GEMM_SMEM = 2 * G_STG * 4;  // 81920 B

template <int MODE>
__global__ void __launch_bounds__(256, 2) gemm_bf16_kernel(
    const float* __restrict__ bias, float* __restrict__ Out)
{
    extern __shared__ uint32_t su[];

    const int tid = threadIdx.x;
    const int warp = tid >> 5, lane = tid & 31;
    const int g = lane >> 2, tg = lane & 3;
    const int wm = warp >> 2, wn = warp & 3;      // 2x4 warps, warp tile 64x32
    const int m0 = blockIdx.y * 128;
    const int n0 = blockIdx.x * 128;

    const __nv_bfloat16* Ah = g_xh;
    const __nv_bfloat16* Al = g_xl;
    const __nv_bfloat16* Bh = (MODE == 0) ? g_wh : g_woh;
    const __nv_bfloat16* Bl = (MODE == 0) ? g_wl : g_wol;

    float acc[4][4][4];
#pragma unroll
    for (int a = 0; a < 4; a++)
#pragma unroll
        for (int b = 0; b < 4; b++)
#pragma unroll
            for (int c = 0; c < 4; c++) acc[a][b][c] = 0.f;

    const int lr = tid >> 1;            // 0..127 (tile row)
    const int lc = (tid & 1) * 8;       // u32 col base 0 or 8
    const __nv_bfloat16* pA_h = Ah + (size_t)(m0 + lr) * NC + lc * 2;
    const __nv_bfloat16* pA_l = Al + (size_t)(m0 + lr) * NC + lc * 2;
    const __nv_bfloat16* pB_h = Bh + (size_t)(n0 + lr) * NC + lc * 2;
    const __nv_bfloat16* pB_l = Bl + (size_t)(n0 + lr) * NC + lc * 2;
    const uint32_t sb = (uint32_t)__cvta_generic_to_shared(su);
    const uint32_t sdst = sb + (lr * 20 + lc) * 4;

    // ldmatrix lane addressing (A-style and B-style)
    const int lm = lane & 7, sel = lane >> 3;
    const int rowA = lm + ((sel & 1) << 3), colA = (sel & 2) << 1;   // +8 rows / +4 u32
    const int rowB = lm + ((sel & 2) << 2), colB = (sel & 1) << 2;
    const uint32_t aH0 = sb + ((wm * 64 + rowA) * 20 + colA) * 4;
    const uint32_t aL0 = aH0 + 2560 * 4;
    const uint32_t bH0 = sb + 5120 * 4 + ((wn * 32 + rowB) * 20 + colB) * 4;
    const uint32_t bL0 = bH0 + 2560 * 4;

#define G_LOAD(S, KT)                                                          \
    {                                                                          \
        uint32_t d0 = sdst + (S) * (G_STG * 4);                                \
        CPA16(d0,                 pA_h + (KT));                                \
        CPA16(d0 + 16,            pA_h + (KT) + 8);                            \
        CPA16(d0 + 2560 * 4,      pA_l + (KT));                                \
        CPA16(d0 + 2560 * 4 + 16, pA_l + (KT) + 8);                            \
        CPA16(d0 + 5120 * 4,      pB_h + (KT));                                \
        CPA16(d0 + 5120 * 4 + 16, pB_h + (KT) + 8);                            \
        CPA16(d0 + 7680 * 4,      pB_l + (KT));                                \
        CPA16(d0 + 7680 * 4 + 16, pB_l + (KT) + 8);                            \
        CPA_COMMIT();                                                          \
    }

    G_LOAD(0, 0);

    for (int c = 0; c < 32; c++) {
        if (c < 31) { G_LOAD((c + 1) & 1, (c + 1) * 32); CPA_WAIT1(); }
        else        { CPA_WAIT0(); }
        __syncthreads();
        const uint32_t stg = (c & 1) * (G_STG * 4);

#pragma unroll
        for (int ks = 0; ks < 2; ks++) {
            const uint32_t ko = stg + ks * 32;
            uint32_t ah[4][4], al[4][4];
#pragma unroll
            for (int mt = 0; mt < 4; mt++) {
                ldsm4(ah[mt], aH0 + ko + mt * 1280);
                ldsm4(al[mt], aL0 + ko + mt * 1280);
            }
#pragma unroll
            for (int j = 0; j < 2; j++) {
                uint32_t bh[4], bl[4];
                ldsm4(bh, bH0 + ko + j * 1280);
                ldsm4(bl, bL0 + ko + j * 1280);
#pragma unroll
                for (int mt = 0; mt < 4; mt++) {
                    mma16(acc[mt][2 * j],     ah[mt], bh[0], bh[1]);
                    mma16(acc[mt][2 * j],     al[mt], bh[0], bh[1]);
                    mma16(acc[mt][2 * j],     ah[mt], bl[0], bl[1]);
                    mma16(acc[mt][2 * j + 1], ah[mt], bh[2], bh[3]);
                    mma16(acc[mt][2 * j + 1], al[mt], bh[2], bh[3]);
                    mma16(acc[mt][2 * j + 1], ah[mt], bl[2], bl[3]);
                }
            }
        }
        __syncthreads();
    }

    // epilogue
#pragma unroll
    for (int mt = 0; mt < 4; mt++) {
        int row = m0 + wm * 64 + mt * 16 + g;
#pragma unroll
        for (int nt = 0; nt < 4; nt++) {
            int colg = blockIdx.x * 128 + wn * 32 + nt * 8 + 2 * tg;
            if (MODE == 0) {
                int sl = colg >> 10, cc = colg & 1023;
                int h = cc >> 6, d = cc & 63;
                int b = row >> 11, t = row & (NT - 1);
                size_t off = (((size_t)(b * NH + h) * NT) + t) * NHS + d;
                if (sl == 2) {
                    *(float2*)(g_v + off) = make_float2(acc[mt][nt][0], acc[mt][nt][1]);
                    *(float2*)(g_v + off + 8 * NHS) = make_float2(acc[mt][nt][2], acc[mt][nt][3]);
                } else {
                    float sc = (sl == 0) ? 8.f : 1.f;   // pre-scale Q by sqrt(HS)
                    __nv_bfloat16* dh = (sl == 0) ? g_qh : g_kh;
                    __nv_bfloat16* dl = (sl == 0) ? g_ql : g_kl;
                    uint32_t ph, pl;
                    split_pack(acc[mt][nt][0] * sc, acc[mt][nt][1] * sc, ph, pl);
                    *(uint32_t*)(dh + off) = ph;
                    *(uint32_t*)(dl + off) = pl;
                    split_pack(acc[mt][nt][2] * sc, acc[mt][nt][3] * sc, ph, pl);
                    *(uint32_t*)(dh + off + 8 * NHS) = ph;
                    *(uint32_t*)(dl + off + 8 * NHS) = pl;
                }
            } else {
                float2 bv = *(const float2*)(bias + colg);
                *(float2*)(Out + (size_t)row * NC + colg) =
                    make_float2(acc[mt][nt][0] + bv.x, acc[mt][nt][1] + bv.y);
                *(float2*)(Out + (size_t)(row + 8) * NC + colg) =
                    make_float2(acc[mt][nt][2] + bv.x, acc[mt][nt][3] + bv.y);
            }
        }
    }
}

// ---------------- flash attention (causal), 3xBF16 + ldmatrix ---------------
__global__ void __launch_bounds__(256, 2) flash_attn_kernel()
{
    extern __shared__ uint32_t su[];
    uint32_t* sQh = su;            // 128*36
    uint32_t* sQl = su + 4608;
    uint32_t* sKh = su + 9216;     // 32*36
    uint32_t* sKl = su + 10368;
    uint32_t* sVh = su + 11520;    // 64*20 (no swizzle; uint4 stores)
    uint32_t* sVl = su + 12800;
    uint32_t* sPh = su + 14080;    // 128*20
    uint32_t* sPl = su + 16640;    // total 19200 u32

    const int tid = threadIdx.x;
    const int warp = tid >> 5, lane = tid & 31;
    const int g = lane >> 2, tg = lane & 3;
    const int qi = (int)gridDim.x - 1 - (int)blockIdx.x;   // longest first
    const int bh = blockIdx.y;

    const size_t base = (size_t)bh * NT * NHS;
    const __nv_bfloat16* Qhg = g_qh + base + (size_t)qi * 128 * NHS;
    const __nv_bfloat16* Qlg = g_ql + base + (size_t)qi * 128 * NHS;
    const __nv_bfloat16* Khg = g_kh + base;
    const __nv_bfloat16* Klg = g_kl + base;
    const float* Vg = g_v + base;

    // ldmatrix lane addressing
    const uint32_t sb = (uint32_t)__cvta_generic_to_shared(su);
    const int lm = lane & 7, sel = lane >> 3;
    const int rowA = lm + ((sel & 1) << 3), colA = (sel & 2) << 1;
    const int rowB = lm + ((sel & 2) << 2), colB = (sel & 1) << 2;
    const uint32_t qH0 = sb + ((warp * 16 + rowA) * 36 + colA) * 4;
    const uint32_t qL0 = qH0 + 4608 * 4;
    const uint32_t kH0 = sb + 9216 * 4 + (rowB * 36 + colB) * 4;
    const uint32_t kL0 = kH0 + 1152 * 4;
    const uint32_t vH0 = sb + 11520 * 4 + (rowB * 20 + colB) * 4;
    const uint32_t vL0 = vH0 + 1280 * 4;
    const uint32_t pH0 = sb + 14080 * 4 + ((warp * 16 + rowA) * 20 + colA) * 4;
    const uint32_t pL0 = pH0 + 2560 * 4;

    // load Q tile (bf16 pairs, already scaled)
    {
        int r = tid >> 1, cc = (tid & 1) * 16;
#pragma unroll
        for (int j = 0; j < 4; j++) {
            int eo = (cc + 4 * j) * 2;
            *(uint4*)&sQh[r * 36 + cc + 4 * j] = *(const uint4*)(Qhg + r * NHS + eo);
            *(uint4*)&sQl[r * 36 + cc + 4 * j] = *(const uint4*)(Qlg + r * NHS + eo);
        }
    }

    float o[8][4];
#pragma unroll
    for (int i = 0; i < 8; i++)
#pragma unroll
        for (int j = 0; j < 4; j++) o[i][j] = 0.f;
    float mr[2] = {-1e30f, -1e30f}, lsum[2] = {0.f, 0.f};

    const int row0 = qi * 128 + warp * 16 + g;
    const int nkt = 4 * qi + 4;

    const int kr = tid >> 3, kc = (tid & 7) * 4;   // K loader: row, u32 col
    const int vd = tid & 63, vq = tid >> 6;        // V loader: dim, quarter
    uint4 rkh, rkl;
    float rv0[4], rv1[4];
#define LD_KV(KT)                                                                  \
    {                                                                              \
        rkh = *(const uint4*)(Khg + (size_t)((KT) * 32 + kr) * NHS + kc * 2);      \
        rkl = *(const uint4*)(Klg + (size_t)((KT) * 32 + kr) * NHS + kc * 2);      \
        _Pragma("unroll") for (int i = 0; i < 4; i++) {                            \
            int kp = vq * 4 + i;                                                   \
            rv0[i] = Vg[(size_t)((KT) * 32 + 2 * kp) * NHS + vd];                  \
            rv1[i] = Vg[(size_t)((KT) * 32 + 2 * kp + 1) * NHS + vd];              \
        }                                                                          \
    }
    LD_KV(0);

    for (int kt = 0; kt < nkt; kt++) {
        __syncthreads();
        *(uint4*)&sKh[kr * 36 + kc] = rkh;
        *(uint4*)&sKl[kr * 36 + kc] = rkl;
        {
            uint4 vh4, vl4;
            split_pack(rv0[0], rv1[0], vh4.x, vl4.x);
            split_pack(rv0[1], rv1[1], vh4.y, vl4.y);
            split_pack(rv0[2], rv1[2], vh4.z, vl4.z);
            split_pack(rv0[3], rv1[3], vh4.w, vl4.w);
            *(uint4*)&sVh[vd * 20 + vq * 4] = vh4;
            *(uint4*)&sVl[vd * 20 + vq * 4] = vl4;
        }
        __syncthreads();
        if (kt + 1 < nkt) LD_KV(kt + 1);

        if (kt * 32 > qi * 128 + warp * 16 + 15) continue;  // fully masked

        // S = Q K^T (16x32 per warp)
        float s[4][4];
#pragma unroll
        for (int i = 0; i < 4; i++)
#pragma unroll
            for (int j = 0; j < 4; j++) s[i][j] = 0.f;

#pragma unroll
        for (int ks = 0; ks < 4; ks++) {
            const uint32_t ko = ks * 32;
            uint32_t qh[4], ql[4];
            ldsm4(qh, qH0 + ko);
            ldsm4(ql, qL0 + ko);
#pragma unroll
            for (int j = 0; j < 2; j++) {
                uint32_t kh[4], kl[4];
                ldsm4(kh, kH0 + ko + j * 2304);
                ldsm4(kl, kL0 + ko + j * 2304);
                mma16(s[2 * j],     qh, kh[0], kh[1]);
                mma16(s[2 * j],     ql, kh[0], kh[1]);
                mma16(s[2 * j],     qh, kl[0], kl[1]);
                mma16(s[2 * j + 1], qh, kh[2], kh[3]);
                mma16(s[2 * j + 1], ql, kh[2], kh[3]);
                mma16(s[2 * j + 1], qh, kl[2], kl[3]);
            }
        }

        // causal mask
        if (kt * 32 + 31 > qi * 128 + warp * 16) {
#pragma unroll
            for (int nt = 0; nt < 4; nt++)
#pragma unroll
                for (int c = 0; c < 4; c++) {
                    int key = kt * 32 + nt * 8 + 2 * tg + (c & 1);
                    int rr = row0 + ((c & 2) ? 8 : 0);
                    if (key > rr) s[nt][c] = -1e30f;
                }
        }

        // online softmax (rows g, g+8)
#pragma unroll
        for (int r = 0; r < 2; r++) {
            const int cb = 2 * r;
            float mx = mr[r];
#pragma unroll
            for (int nt = 0; nt < 4; nt++)
                mx = fmaxf(mx, fmaxf(s[nt][cb], s[nt][cb + 1]));
            mx = fmaxf(mx, __shfl_xor_sync(0xffffffffu, mx, 1));
            mx = fmaxf(mx, __shfl_xor_sync(0xffffffffu, mx, 2));
            float alpha = __expf(mr[r] - mx);
            float rs = 0.f;
#pragma unroll
            for (int nt = 0; nt < 4; nt++) {
                float p0 = __expf(s[nt][cb] - mx);
                float p1 = __expf(s[nt][cb + 1] - mx);
                s[nt][cb] = p0; s[nt][cb + 1] = p1;
                rs += p0 + p1;
            }
            rs += __shfl_xor_sync(0xffffffffu, rs, 1);
            rs += __shfl_xor_sync(0xffffffffu, rs, 2);
            lsum[r] = lsum[r] * alpha + rs;
            mr[r] = mx;
#pragma unroll
            for (int nt = 0; nt < 8; nt++) {
                o[nt][cb] *= alpha; o[nt][cb + 1] *= alpha;
            }
        }

        // stage P split+packed (warp-private rows; conflict-free scalar stores)
#pragma unroll
        for (int nt = 0; nt < 4; nt++) {
            uint32_t ph, pl;
            split_pack(s[nt][0], s[nt][1], ph, pl);
            sPh[(warp * 16 + g) * 20 + nt * 4 + tg] = ph;
            sPl[(warp * 16 + g) * 20 + nt * 4 + tg] = pl;
            split_pack(s[nt][2], s[nt][3], ph, pl);
            sPh[(warp * 16 + g + 8) * 20 + nt * 4 + tg] = ph;
            sPl[(warp * 16 + g + 8) * 20 + nt * 4 + tg] = pl;
        }
        __syncwarp();

        // O += P V
#pragma unroll
        for (int ks = 0; ks < 2; ks++) {
            const uint32_t ko = ks * 32;
            uint32_t ph[4], pl[4];
            ldsm4(ph, pH0 + ko);
            ldsm4(pl, pL0 + ko);
#pragma unroll
            for (int j = 0; j < 4; j++) {
                uint32_t vh[4], vl[4];
                ldsm4(vh, vH0 + ko + j * 1280);
                ldsm4(vl, vL0 + ko + j * 1280);
                mma16(o[2 * j],     ph, vh[0], vh[1]);
                mma16(o[2 * j],     pl, vh[0], vh[1]);
                mma16(o[2 * j],     ph, vl[0], vl[1]);
                mma16(o[2 * j + 1], ph, vh[2], vh[3]);
                mma16(o[2 * j + 1], pl, vh[2], vh[3]);
                mma16(o[2 * j + 1], ph, vl[2], vl[3]);
            }
        }
    }

    // normalize + write attn-out bf16-split into g_xh/g_xl [B,T,C]
    const int bb = bh >> 4, hh = bh & 15;
    const float inv0 = 1.f / lsum[0], inv1 = 1.f / lsum[1];
#pragma unroll
    for (int nt = 0; nt < 8; nt++) {
        int col = hh * 64 + nt * 8 + 2 * tg;
        size_t off = (size_t)(bb * NT + row0) * NC + col;
        uint32_t ph, pl;
        split_pack(o[nt][0] * inv0, o[nt][1] * inv0, ph, pl);
        *(uint32_t*)(g_xh + off) = ph;
        *(uint32_t*)(g_xl + off) = pl;
        split_pack(o[nt][2] * inv1, o[nt][3] * inv1, ph, pl);
        *(uint32_t*)(g_xh + off + 8 * NC) = ph;
        *(uint32_t*)(g_xl + off + 8 * NC) = pl;
    }
}

// ---------------- launcher --------------------------------------------------
extern "C" void kernel_launch(void* const* d_in, const int* in_sizes, int n_in,
                              void* d_out, int out_size)
{
    const float* x  = (const float*)d_in[0];
    const float* Wq = (const float*)d_in[1];
    const float* Wk = (const float*)d_in[2];
    const float* Wv = (const float*)d_in[3];
    const float* Wo = (const float*)d_in[4];
    const float* bo = (const float*)d_in[5];
    float* out = (float*)d_out;

    const int smem_flash = 19200 * 4;   // 75 KB
    cudaFuncSetAttribute(gemm_bf16_kernel<0>, cudaFuncAttributeMaxDynamicSharedMemorySize, GEMM_SMEM);
    cudaFuncSetAttribute(gemm_bf16_kernel<1>, cudaFuncAttributeMaxDynamicSharedMemorySize, GEMM_SMEM);
    cudaFuncSetAttribute(flash_attn_kernel, cudaFuncAttributeMaxDynamicSharedMemorySize, smem_flash);

    // 1) pre-split x + all weights to bf16 hi/lo (one fused launch)
    split_all_kernel<<<12288, 256>>>(x, Wq, Wk, Wv, Wo);

    // 2) QKV projection -> g_qh/ql, g_kh/kl (bf16-split), g_v (f32)
    gemm_bf16_kernel<0><<<dim3(24, 64), 256, GEMM_SMEM>>>(nullptr, nullptr);

    // 3) causal flash attention -> g_xh/g_xl (attn out, bf16-split)
    flash_attn_kernel<<<dim3(NT / 128, NB * NH), 256, smem_flash>>>();

    // 4) out projection + bias -> d_out
    gemm_bf16_kernel<1><<<dim3(8, 64), 256, GEMM_SMEM>>>(bo, out);
}